// round 6
// baseline (speedup 1.0000x reference)
#include <cuda_runtime.h>
#include <cuda_bf16.h>
#include <cuda_fp16.h>
#include <cstdint>

#define NMAX 100000
#define EMAX 1600000
#define INC  128
#define HID  128
#define OUTC 64
#define EPS  1e-5f

// ---------------- scratch (no allocations allowed) ----------------
__device__ int    g_cnt[NMAX];
__device__ int    g_rowptr[NMAX + 1];
__device__ int    g_fill[NMAX];
__device__ int    g_col[EMAX];
__device__ float  g_dinv[NMAX];
__device__ int    g_bsum[128];
__device__ int    g_ctr1, g_ctr2;
__device__ __half g_h1h[(size_t)NMAX * HID];   // x@W1 (UNscaled), fp16
__device__ float  g_a1[(size_t)NMAX * HID];    // aggregated layer-1 (pre-BN), fp32
__device__ __half g_h2h[(size_t)NMAX * OUTC];  // (relu(bn1)@W2)*dinv, fp16
__device__ float  g_stats1[4 * HID];           // sum | sq | s | t
__device__ float  g_stats2[4 * OUTC];

// ---------------- helpers ----------------
__device__ __forceinline__ uint32_t smem_u32(const void* p) {
    uint32_t a;
    asm("{ .reg .u64 t; cvta.to.shared.u64 t, %1; cvt.u32.u64 %0, t; }" : "=r"(a) : "l"(p));
    return a;
}
__device__ __forceinline__ void ldmatrix_x4(uint32_t* r, uint32_t addr) {
    asm volatile("ldmatrix.sync.aligned.m8n8.x4.shared.b16 {%0,%1,%2,%3}, [%4];"
                 : "=r"(r[0]), "=r"(r[1]), "=r"(r[2]), "=r"(r[3]) : "r"(addr));
}
__device__ __forceinline__ void mma_bf16(float* c, const uint32_t* a, uint32_t b0, uint32_t b1) {
    asm volatile(
        "mma.sync.aligned.m16n8k16.row.col.f32.bf16.bf16.f32 "
        "{%0,%1,%2,%3}, {%4,%5,%6,%7}, {%8,%9}, {%0,%1,%2,%3};"
        : "+f"(c[0]), "+f"(c[1]), "+f"(c[2]), "+f"(c[3])
        : "r"(a[0]), "r"(a[1]), "r"(a[2]), "r"(a[3]), "r"(b0), "r"(b1));
}

// ---------------- init ----------------
__global__ void zero_kernel(int n) {
    int i = blockIdx.x * blockDim.x + threadIdx.x;
    if (i < n)        g_cnt[i] = 0;
    if (i < 4 * HID)  g_stats1[i] = 0.f;
    if (i < 4 * OUTC) g_stats2[i] = 0.f;
    if (i == 0) { g_ctr1 = 0; g_ctr2 = 0; }
}

// ---------------- degree count ----------------
__global__ void count_kernel(const int* __restrict__ dst, int E) {
    int i = blockIdx.x * blockDim.x + threadIdx.x;
    if (i < E) atomicAdd(&g_cnt[dst[i]], 1);
}

// ---------------- 2-pass parallel scan (block scan fused into pass 2) ----------------
__global__ void scan1_kernel(int n) {
    __shared__ int ws[32];
    int tid = threadIdx.x, lane = tid & 31, w = tid >> 5;
    int i = blockIdx.x * 1024 + tid;
    int v = (i < n) ? g_cnt[i] : 0;
    int x = v;
    #pragma unroll
    for (int off = 1; off < 32; off <<= 1) {
        int y = __shfl_up_sync(0xffffffffu, x, off);
        if (lane >= off) x += y;
    }
    if (lane == 31) ws[w] = x;
    __syncthreads();
    if (w == 0) {
        int y = ws[lane];
        #pragma unroll
        for (int off = 1; off < 32; off <<= 1) {
            int z = __shfl_up_sync(0xffffffffu, y, off);
            if (lane >= off) y += z;
        }
        ws[lane] = y;
    }
    __syncthreads();
    int incl = x + (w ? ws[w - 1] : 0);
    if (i < n) g_fill[i] = incl - v;
    if (tid == 1023) g_bsum[blockIdx.x] = incl;
}
__global__ void scan3_kernel(int n, int nb) {
    __shared__ int excl[128];
    __shared__ int wsum[4];
    int tid = threadIdx.x, lane = tid & 31, w = tid >> 5;
    // every block redundantly scans the (<=128) block sums
    int xv = 0, vv = 0;
    if (tid < 128) {
        vv = (tid < nb) ? g_bsum[tid] : 0;
        xv = vv;
        #pragma unroll
        for (int off = 1; off < 32; off <<= 1) {
            int y = __shfl_up_sync(0xffffffffu, xv, off);
            if (lane >= off) xv += y;
        }
        if (lane == 31) wsum[w] = xv;
    }
    __syncthreads();
    if (tid < 128) {
        int add = 0;
        #pragma unroll
        for (int j = 0; j < 4; j++) if (j < w) add += wsum[j];
        excl[tid] = xv - vv + add;
    }
    __syncthreads();
    int off = excl[blockIdx.x];
    int i = blockIdx.x * 1024 + tid;
    if (i < n) {
        int c = g_cnt[i];
        int ex = g_fill[i] + off;
        g_fill[i] = ex;
        g_rowptr[i + 1] = ex + c;
        g_dinv[i] = rsqrtf((float)(c + 1));
        if (i == 0) g_rowptr[0] = 0;
    }
}

// ---------------- CSR fill ----------------
__global__ void fill_kernel(const int* __restrict__ src, const int* __restrict__ dst, int E) {
    int i = blockIdx.x * blockDim.x + threadIdx.x;
    if (i < E) {
        int d = dst[i];
        int pos = atomicAdd(&g_fill[d], 1);
        g_col[pos] = src[i];
    }
}

// ---------------- HMMA bf16 GEMM ----------------
// A and W split into bf16 hi/lo; D = Ah*Wh + Al*Wh + Ah*Wl accumulated in fp32.
// PRE_BN: A element -> relu(a*s[k]+t[k]). DINV: epilogue scales row by dinv[row].
#define ASTR 136
template <int TN, bool PRE_BN, bool DINV>
__global__ __launch_bounds__(256)
void mmagemm_kernel(const float* __restrict__ Aext, const float* __restrict__ W, int M) {
    extern __shared__ char smem[];
    const uint32_t SM_ST = 0;
    const uint32_t A_HI  = 1024;
    const uint32_t A_LO  = A_HI + 128 * ASTR * 2;
    const uint32_t B_HI  = A_LO + 128 * ASTR * 2;
    const uint32_t B_LO  = B_HI + TN * ASTR * 2;

    uint32_t sb = smem_u32(smem);
    int tid = threadIdx.x, wid = tid >> 5, lane = tid & 31;
    int m0 = blockIdx.x * 128;

    if (PRE_BN && tid < 256) {
        float v = (tid < 128) ? g_stats1[2 * HID + tid] : g_stats1[3 * HID + (tid - 128)];
        *(float*)(smem + SM_ST + tid * 4) = v;
    }

    const float* Asrc = PRE_BN ? g_a1 : Aext;
    __half* Cout = PRE_BN ? g_h2h : g_h1h;

    const float* s = (const float*)(smem + SM_ST);
    const float* t = s + 128;
    if (PRE_BN) __syncthreads();
    #pragma unroll
    for (int it = 0; it < 16; ++it) {
        int idx = tid + it * 256;
        int row = idx >> 5;
        int col = (idx & 31) << 2;
        float4 v = make_float4(0.f, 0.f, 0.f, 0.f);
        if (m0 + row < M) v = *(const float4*)&Asrc[(size_t)(m0 + row) * 128 + col];
        if (PRE_BN) {
            v.x = fmaxf(fmaf(v.x, s[col + 0], t[col + 0]), 0.f);
            v.y = fmaxf(fmaf(v.y, s[col + 1], t[col + 1]), 0.f);
            v.z = fmaxf(fmaf(v.z, s[col + 2], t[col + 2]), 0.f);
            v.w = fmaxf(fmaf(v.w, s[col + 3], t[col + 3]), 0.f);
        }
        __nv_bfloat162 h01 = __floats2bfloat162_rn(v.x, v.y);
        __nv_bfloat162 h23 = __floats2bfloat162_rn(v.z, v.w);
        __nv_bfloat162 l01 = __floats2bfloat162_rn(v.x - __bfloat162float(h01.x),
                                                   v.y - __bfloat162float(h01.y));
        __nv_bfloat162 l23 = __floats2bfloat162_rn(v.z - __bfloat162float(h23.x),
                                                   v.w - __bfloat162float(h23.y));
        uint32_t off = (uint32_t)row * (ASTR * 2) + (uint32_t)col * 2;
        *(__nv_bfloat162*)(smem + A_HI + off)     = h01;
        *(__nv_bfloat162*)(smem + A_HI + off + 4) = h23;
        *(__nv_bfloat162*)(smem + A_LO + off)     = l01;
        *(__nv_bfloat162*)(smem + A_LO + off + 4) = l23;
    }
    for (int idx = tid; idx < 128 * TN; idx += 256) {
        int k = idx / TN, n = idx % TN;
        float w = W[idx];
        __nv_bfloat16 hi = __float2bfloat16_rn(w);
        __nv_bfloat16 lo = __float2bfloat16_rn(w - __bfloat162float(hi));
        uint32_t off = (uint32_t)n * (ASTR * 2) + (uint32_t)k * 2;
        *(__nv_bfloat16*)(smem + B_HI + off) = hi;
        *(__nv_bfloat16*)(smem + B_LO + off) = lo;
    }
    __syncthreads();

    constexpr int WN   = TN / 2;
    constexpr int NSUB = WN / 8;
    int m_base = (wid & 3) * 32;
    int n_base = (wid >> 2) * WN;
    int g = lane >> 2, tt = lane & 3;

    float acc[2][NSUB][4];
    #pragma unroll
    for (int mi = 0; mi < 2; mi++)
        #pragma unroll
        for (int ni = 0; ni < NSUB; ni++)
            #pragma unroll
            for (int j = 0; j < 4; j++) acc[mi][ni][j] = 0.f;

    uint32_t a_row = (uint32_t)(m_base + (lane & 15));
    uint32_t a_cb  = (uint32_t)((lane >> 4) * 8);

    #pragma unroll
    for (int term = 0; term < 3; ++term) {
        uint32_t Abase = sb + ((term == 1) ? A_LO : A_HI);
        uint32_t Bbase = ((term == 2) ? B_LO : B_HI);
        #pragma unroll
        for (int ks = 0; ks < 8; ++ks) {
            int k0 = ks * 16;
            uint32_t af[2][4];
            #pragma unroll
            for (int mi = 0; mi < 2; mi++) {
                uint32_t addr = Abase + (a_row + mi * 16) * (ASTR * 2) + (a_cb + k0) * 2;
                ldmatrix_x4(af[mi], addr);
            }
            const char* brow = smem + Bbase + (uint32_t)(n_base + g) * (ASTR * 2) + (uint32_t)(k0 + 2 * tt) * 2;
            #pragma unroll
            for (int ni = 0; ni < NSUB; ni++) {
                uint32_t b0 = *(const uint32_t*)(brow + ni * 8 * (ASTR * 2));
                uint32_t b1 = *(const uint32_t*)(brow + ni * 8 * (ASTR * 2) + 16);
                mma_bf16(acc[0][ni], af[0], b0, b1);
                mma_bf16(acc[1][ni], af[1], b0, b1);
            }
        }
    }

    #pragma unroll
    for (int mi = 0; mi < 2; mi++) {
        int r0 = m0 + m_base + mi * 16 + g;
        int r1 = r0 + 8;
        float d0 = 1.f, d1 = 1.f;
        if (DINV) {
            d0 = (r0 < M) ? g_dinv[r0] : 0.f;
            d1 = (r1 < M) ? g_dinv[r1] : 0.f;
        }
        #pragma unroll
        for (int ni = 0; ni < NSUB; ni++) {
            int col = n_base + ni * 8 + 2 * tt;
            if (r0 < M)
                *(__half2*)&Cout[(size_t)r0 * TN + col] =
                    __floats2half2_rn(acc[mi][ni][0] * d0, acc[mi][ni][1] * d0);
            if (r1 < M)
                *(__half2*)&Cout[(size_t)r1 * TN + col] =
                    __floats2half2_rn(acc[mi][ni][2] * d1, acc[mi][ni][3] * d1);
        }
    }
}

// ---------------- aggregation helpers ----------------
__device__ __forceinline__ float4 h4_to_f4(uint2 u) {
    float2 a = __half22float2(*(__half2*)&u.x);
    float2 b = __half22float2(*(__half2*)&u.y);
    return make_float4(a.x, a.y, b.x, b.y);
}

// ---------------- aggregation, 128 cols: h1 UNscaled -> apply dinv[src] per edge ----------------
// Last block to finish also computes BN1 s/t (fused bnparams).
__global__ __launch_bounds__(256)
void agg128_kernel(const float* __restrict__ b, const float* __restrict__ gamma,
                   const float* __restrict__ beta, int n, float invN) {
    int gwarp  = (blockIdx.x * blockDim.x + threadIdx.x) >> 5;
    int lane   = threadIdx.x & 31;
    int nwarps = (gridDim.x * blockDim.x) >> 5;
    const uint2* base = (const uint2*)g_h1h;
    float4 bb = ((const float4*)b)[lane];
    float4 sum = make_float4(0, 0, 0, 0), sq = make_float4(0, 0, 0, 0);

    for (int node = gwarp; node < n; node += nwarps) {
        int e0 = g_rowptr[node], e1 = g_rowptr[node + 1];
        float dn = g_dinv[node];
        float4 h = h4_to_f4(base[(size_t)node * 32 + lane]);  // self-loop
        float4 acc;
        acc.x = h.x * dn; acc.y = h.y * dn; acc.z = h.z * dn; acc.w = h.w * dn;
        int e = e0;
        for (; e + 4 <= e1; e += 4) {
            int i0 = g_col[e], i1 = g_col[e + 1], i2 = g_col[e + 2], i3 = g_col[e + 3];
            float d0v = g_dinv[i0], d1v = g_dinv[i1], d2v = g_dinv[i2], d3v = g_dinv[i3];
            float4 v0 = h4_to_f4(base[(size_t)i0 * 32 + lane]);
            float4 v1 = h4_to_f4(base[(size_t)i1 * 32 + lane]);
            float4 v2 = h4_to_f4(base[(size_t)i2 * 32 + lane]);
            float4 v3 = h4_to_f4(base[(size_t)i3 * 32 + lane]);
            acc.x += v0.x * d0v + v1.x * d1v + v2.x * d2v + v3.x * d3v;
            acc.y += v0.y * d0v + v1.y * d1v + v2.y * d2v + v3.y * d3v;
            acc.z += v0.z * d0v + v1.z * d1v + v2.z * d2v + v3.z * d3v;
            acc.w += v0.w * d0v + v1.w * d1v + v2.w * d2v + v3.w * d3v;
        }
        for (; e < e1; e++) {
            int i0 = g_col[e];
            float dv = g_dinv[i0];
            float4 v = h4_to_f4(base[(size_t)i0 * 32 + lane]);
            acc.x += v.x * dv; acc.y += v.y * dv; acc.z += v.z * dv; acc.w += v.w * dv;
        }
        float4 o;
        o.x = fmaf(acc.x, dn, bb.x); o.y = fmaf(acc.y, dn, bb.y);
        o.z = fmaf(acc.z, dn, bb.z); o.w = fmaf(acc.w, dn, bb.w);
        ((float4*)g_a1)[(size_t)node * 32 + lane] = o;
        sum.x += o.x; sum.y += o.y; sum.z += o.z; sum.w += o.w;
        sq.x += o.x * o.x; sq.y += o.y * o.y; sq.z += o.z * o.z; sq.w += o.w * o.w;
    }
    __shared__ float ssum[HID], ssq[HID];
    int t = threadIdx.x;
    if (t < HID) { ssum[t] = 0.f; ssq[t] = 0.f; }
    __syncthreads();
    int c0 = lane * 4;
    atomicAdd(&ssum[c0 + 0], sum.x); atomicAdd(&ssum[c0 + 1], sum.y);
    atomicAdd(&ssum[c0 + 2], sum.z); atomicAdd(&ssum[c0 + 3], sum.w);
    atomicAdd(&ssq[c0 + 0], sq.x);  atomicAdd(&ssq[c0 + 1], sq.y);
    atomicAdd(&ssq[c0 + 2], sq.z);  atomicAdd(&ssq[c0 + 3], sq.w);
    __syncthreads();
    if (t < HID) {
        atomicAdd(&g_stats1[t], ssum[t]);
        atomicAdd(&g_stats1[HID + t], ssq[t]);
    }
    // fused BN1 param computation in the last block
    __threadfence();
    __shared__ int isLast;
    __syncthreads();
    if (t == 0) isLast = (atomicAdd(&g_ctr1, 1) == (int)gridDim.x - 1);
    __syncthreads();
    if (isLast && t < HID) {
        float mean = g_stats1[t] * invN;
        float var  = g_stats1[HID + t] * invN - mean * mean;
        float sc = gamma[t] * rsqrtf(var + EPS);
        g_stats1[2 * HID + t] = sc;
        g_stats1[3 * HID + t] = beta[t] - mean * sc;
    }
}

// ---------------- aggregation, 64 cols: h2 pre-scaled by dinv[src] ----------------
__global__ __launch_bounds__(256)
void agg64_kernel(const float* __restrict__ b, const float* __restrict__ gamma,
                  const float* __restrict__ beta, float* __restrict__ out,
                  int n, float invN) {
    int gwarp  = (blockIdx.x * blockDim.x + threadIdx.x) >> 5;
    int lane   = threadIdx.x & 31;
    int nwarps = (gridDim.x * blockDim.x) >> 5;
    const __half2* base = (const __half2*)g_h2h;
    float2 bb = ((const float2*)b)[lane];
    float2 sum = make_float2(0, 0), sq = make_float2(0, 0);

    for (int node = gwarp; node < n; node += nwarps) {
        int e0 = g_rowptr[node], e1 = g_rowptr[node + 1];
        float2 acc = __half22float2(base[(size_t)node * 32 + lane]);
        int e = e0;
        for (; e + 4 <= e1; e += 4) {
            int i0 = g_col[e], i1 = g_col[e + 1], i2 = g_col[e + 2], i3 = g_col[e + 3];
            float2 v0 = __half22float2(base[(size_t)i0 * 32 + lane]);
            float2 v1 = __half22float2(base[(size_t)i1 * 32 + lane]);
            float2 v2 = __half22float2(base[(size_t)i2 * 32 + lane]);
            float2 v3 = __half22float2(base[(size_t)i3 * 32 + lane]);
            acc.x += (v0.x + v1.x) + (v2.x + v3.x);
            acc.y += (v0.y + v1.y) + (v2.y + v3.y);
        }
        for (; e < e1; e++) {
            float2 v = __half22float2(base[(size_t)g_col[e] * 32 + lane]);
            acc.x += v.x; acc.y += v.y;
        }
        float d = g_dinv[node];
        float2 o;
        o.x = fmaf(acc.x, d, bb.x); o.y = fmaf(acc.y, d, bb.y);
        ((float2*)out)[(size_t)node * 32 + lane] = o;
        sum.x += o.x; sum.y += o.y;
        sq.x += o.x * o.x; sq.y += o.y * o.y;
    }
    __shared__ float ssum[OUTC], ssq[OUTC];
    int t = threadIdx.x;
    if (t < OUTC) { ssum[t] = 0.f; ssq[t] = 0.f; }
    __syncthreads();
    int c0 = lane * 2;
    atomicAdd(&ssum[c0 + 0], sum.x); atomicAdd(&ssum[c0 + 1], sum.y);
    atomicAdd(&ssq[c0 + 0], sq.x);  atomicAdd(&ssq[c0 + 1], sq.y);
    __syncthreads();
    if (t < OUTC) {
        atomicAdd(&g_stats2[t], ssum[t]);
        atomicAdd(&g_stats2[OUTC + t], ssq[t]);
    }
    __threadfence();
    __shared__ int isLast;
    __syncthreads();
    if (t == 0) isLast = (atomicAdd(&g_ctr2, 1) == (int)gridDim.x - 1);
    __syncthreads();
    if (isLast && t < OUTC) {
        float mean = g_stats2[t] * invN;
        float var  = g_stats2[OUTC + t] * invN - mean * mean;
        float sc = gamma[t] * rsqrtf(var + EPS);
        g_stats2[2 * OUTC + t] = sc;
        g_stats2[3 * OUTC + t] = beta[t] - mean * sc;
    }
}

// ---------------- apply final BN2 in place on d_out ----------------
__global__ void bn2_apply_kernel(float* __restrict__ out, int total4) {
    int i = blockIdx.x * blockDim.x + threadIdx.x;
    if (i < total4) {
        float4 v = ((float4*)out)[i];
        int c = (i & 15) * 4;
        v.x = fmaf(v.x, g_stats2[2 * OUTC + c + 0], g_stats2[3 * OUTC + c + 0]);
        v.y = fmaf(v.y, g_stats2[2 * OUTC + c + 1], g_stats2[3 * OUTC + c + 1]);
        v.z = fmaf(v.z, g_stats2[2 * OUTC + c + 2], g_stats2[3 * OUTC + c + 2]);
        v.w = fmaf(v.w, g_stats2[2 * OUTC + c + 3], g_stats2[3 * OUTC + c + 3]);
        ((float4*)out)[i] = v;
    }
}

extern "C" void kernel_launch(void* const* d_in, const int* in_sizes, int n_in,
                              void* d_out, int out_size) {
    const float* x      = (const float*)d_in[0];
    const float* W1     = (const float*)d_in[1];
    const float* b1     = (const float*)d_in[2];
    const float* gamma1 = (const float*)d_in[3];
    const float* beta1  = (const float*)d_in[4];
    const float* W2     = (const float*)d_in[5];
    const float* b2     = (const float*)d_in[6];
    const float* gamma2 = (const float*)d_in[7];
    const float* beta2  = (const float*)d_in[8];
    const int*   ei     = (const int*)d_in[9];
    float*       out    = (float*)d_out;

    int N = in_sizes[0] / INC;     // 100000
    int E = in_sizes[9] / 2;       // 1600000
    const int* src = ei;
    const int* dst = ei + E;
    float invN = 1.0f / (float)N;

    const int SMEM1 = 1024 + 2 * 128 * ASTR * 2 + 2 * 128 * ASTR * 2;  // 140288
    const int SMEM2 = 1024 + 2 * 128 * ASTR * 2 + 2 * 64 * ASTR * 2;   // 105472

    static cudaStream_t s2 = nullptr;
    static cudaEvent_t  ev0 = nullptr, ev1 = nullptr;
    if (!s2) {
        cudaFuncSetAttribute(mmagemm_kernel<128, false, false>,
                             cudaFuncAttributeMaxDynamicSharedMemorySize, SMEM1);
        cudaFuncSetAttribute(mmagemm_kernel<64, true, true>,
                             cudaFuncAttributeMaxDynamicSharedMemorySize, SMEM2);
        cudaStreamCreateWithFlags(&s2, cudaStreamNonBlocking);
        cudaEventCreateWithFlags(&ev0, cudaEventDisableTiming);
        cudaEventCreateWithFlags(&ev1, cudaEventDisableTiming);
    }

    int nb = (N + 1023) / 1024;
    int gblk = (N + 127) / 128;

    // ---- fork: GEMM1 (pure function of x, W1) on side stream ----
    cudaEventRecord(ev0, 0);
    cudaStreamWaitEvent(s2, ev0, 0);
    mmagemm_kernel<128, false, false><<<gblk, 256, SMEM1, s2>>>(x, W1, N);
    cudaEventRecord(ev1, s2);

    // ---- main branch: CSR build + degrees ----
    zero_kernel<<<(N + 255) / 256, 256>>>(N);
    count_kernel<<<(E + 255) / 256, 256>>>(dst, E);
    scan1_kernel<<<nb, 1024>>>(N);
    scan3_kernel<<<nb, 1024>>>(N, nb);
    fill_kernel<<<(E + 255) / 256, 256>>>(src, dst, E);

    // ---- join ----
    cudaStreamWaitEvent(0, ev1, 0);

    // aggregate layer 1 (+bias, +BN1 stats, +fused BN1 params)
    agg128_kernel<<<1024, 256>>>(b1, gamma1, beta1, N, invN);
    // h2 = (relu(bn1(a1)) @ W2) * dinv -> fp16
    mmagemm_kernel<64, true, true><<<gblk, 256, SMEM2>>>(nullptr, W2, N);
    // aggregate layer 2 into d_out (+bias, +BN2 stats, +fused BN2 params)
    agg64_kernel<<<1024, 256>>>(b2, gamma2, beta2, out, N, invN);
    // apply BN2 affine in place
    int total4 = N * OUTC / 4;
    bn2_apply_kernel<<<(total4 + 255) / 256, 256>>>(out, total4);
}

// round 8
// speedup vs baseline: 1.0864x; 1.0864x over previous
#include <cuda_runtime.h>
#include <cuda_bf16.h>
#include <cuda_fp16.h>
#include <cstdint>

#define NMAX 100000
#define EMAX 1600000
#define INC  128
#define HID  128
#define OUTC 64
#define EPS  1e-5f

// ---------------- scratch (no allocations allowed) ----------------
__device__ int    g_cnt[NMAX];
__device__ int    g_rowptr[NMAX + 1];
__device__ int    g_fill[NMAX];
__device__ int    g_col[EMAX];
__device__ float  g_dinv[NMAX];
__device__ int    g_bsum[128];
__device__ int    g_ctr1, g_ctr2, g_flag2;
__device__ __half g_h1h[(size_t)NMAX * HID];   // x@W1, then scaled by dinv[row]
__device__ float  g_a1[(size_t)NMAX * HID];    // aggregated layer-1 (pre-BN), fp32
__device__ __half g_h2h[(size_t)NMAX * OUTC];  // (relu(bn1)@W2)*dinv, fp16
__device__ float  g_stats1[4 * HID];           // sum | sq | s | t
__device__ float  g_stats2[4 * OUTC];

// ---------------- helpers ----------------
__device__ __forceinline__ uint32_t smem_u32(const void* p) {
    uint32_t a;
    asm("{ .reg .u64 t; cvta.to.shared.u64 t, %1; cvt.u32.u64 %0, t; }" : "=r"(a) : "l"(p));
    return a;
}
__device__ __forceinline__ void ldmatrix_x4(uint32_t* r, uint32_t addr) {
    asm volatile("ldmatrix.sync.aligned.m8n8.x4.shared.b16 {%0,%1,%2,%3}, [%4];"
                 : "=r"(r[0]), "=r"(r[1]), "=r"(r[2]), "=r"(r[3]) : "r"(addr));
}
__device__ __forceinline__ void mma_bf16(float* c, const uint32_t* a, uint32_t b0, uint32_t b1) {
    asm volatile(
        "mma.sync.aligned.m16n8k16.row.col.f32.bf16.bf16.f32 "
        "{%0,%1,%2,%3}, {%4,%5,%6,%7}, {%8,%9}, {%0,%1,%2,%3};"
        : "+f"(c[0]), "+f"(c[1]), "+f"(c[2]), "+f"(c[3])
        : "r"(a[0]), "r"(a[1]), "r"(a[2]), "r"(a[3]), "r"(b0), "r"(b1));
}

// ---------------- init ----------------
__global__ void zero_kernel(int n) {
    int i = blockIdx.x * blockDim.x + threadIdx.x;
    if (i < n)        g_cnt[i] = 0;
    if (i < 4 * HID)  g_stats1[i] = 0.f;
    if (i < 4 * OUTC) g_stats2[i] = 0.f;
    if (i == 0) { g_ctr1 = 0; g_ctr2 = 0; g_flag2 = 0; }
}

// ---------------- degree count ----------------
__global__ void count_kernel(const int* __restrict__ dst, int E) {
    int i = blockIdx.x * blockDim.x + threadIdx.x;
    if (i < E) atomicAdd(&g_cnt[dst[i]], 1);
}

// ---------------- 2-pass parallel scan ----------------
__global__ void scan1_kernel(int n) {
    __shared__ int ws[32];
    int tid = threadIdx.x, lane = tid & 31, w = tid >> 5;
    int i = blockIdx.x * 1024 + tid;
    int v = (i < n) ? g_cnt[i] : 0;
    int x = v;
    #pragma unroll
    for (int off = 1; off < 32; off <<= 1) {
        int y = __shfl_up_sync(0xffffffffu, x, off);
        if (lane >= off) x += y;
    }
    if (lane == 31) ws[w] = x;
    __syncthreads();
    if (w == 0) {
        int y = ws[lane];
        #pragma unroll
        for (int off = 1; off < 32; off <<= 1) {
            int z = __shfl_up_sync(0xffffffffu, y, off);
            if (lane >= off) y += z;
        }
        ws[lane] = y;
    }
    __syncthreads();
    int incl = x + (w ? ws[w - 1] : 0);
    if (i < n) g_fill[i] = incl - v;
    if (tid == 1023) g_bsum[blockIdx.x] = incl;
}
__global__ void scan3_kernel(int n, int nb) {
    __shared__ int excl[128];
    __shared__ int wsum[4];
    int tid = threadIdx.x, lane = tid & 31, w = tid >> 5;
    int xv = 0, vv = 0;
    if (tid < 128) {
        vv = (tid < nb) ? g_bsum[tid] : 0;
        xv = vv;
        #pragma unroll
        for (int off = 1; off < 32; off <<= 1) {
            int y = __shfl_up_sync(0xffffffffu, xv, off);
            if (lane >= off) xv += y;
        }
        if (lane == 31) wsum[w] = xv;
    }
    __syncthreads();
    if (tid < 128) {
        int add = 0;
        #pragma unroll
        for (int j = 0; j < 4; j++) if (j < w) add += wsum[j];
        excl[tid] = xv - vv + add;
    }
    __syncthreads();
    int off = excl[blockIdx.x];
    int i = blockIdx.x * 1024 + tid;
    if (i < n) {
        int c = g_cnt[i];
        int ex = g_fill[i] + off;
        g_fill[i] = ex;
        g_rowptr[i + 1] = ex + c;
        g_dinv[i] = rsqrtf((float)(c + 1));
        if (i == 0) g_rowptr[0] = 0;
    }
}

// ---------------- CSR fill ----------------
__global__ void fill_kernel(const int* __restrict__ src, const int* __restrict__ dst, int E) {
    int i = blockIdx.x * blockDim.x + threadIdx.x;
    if (i < E) {
        int d = dst[i];
        int pos = atomicAdd(&g_fill[d], 1);
        g_col[pos] = src[i];
    }
}

// ---------------- scale h1 rows by dinv[row] (fp16 in place) ----------------
__global__ void scaleh1_kernel(int total16) {  // total16 = N*16 uint4s (8 halves each)
    int i = blockIdx.x * blockDim.x + threadIdx.x;
    if (i < total16) {
        int row = i >> 4;
        float d = g_dinv[row];
        uint4 u = ((const uint4*)g_h1h)[i];
        __half2* h = (__half2*)&u;
        #pragma unroll
        for (int j = 0; j < 4; j++) {
            float2 f = __half22float2(h[j]);
            h[j] = __floats2half2_rn(f.x * d, f.y * d);
        }
        ((uint4*)g_h1h)[i] = u;
    }
}

// ---------------- HMMA bf16 GEMM ----------------
// A and W split into bf16 hi/lo; D = Ah*Wh + Al*Wh + Ah*Wl accumulated in fp32.
// PRE_BN: A element -> relu(a*s[k]+t[k]). DINV: epilogue scales row by dinv[row].
#define ASTR 136
template <int TN, bool PRE_BN, bool DINV>
__global__ __launch_bounds__(256)
void mmagemm_kernel(const float* __restrict__ Aext, const float* __restrict__ W, int M) {
    extern __shared__ char smem[];
    const uint32_t SM_ST = 0;
    const uint32_t A_HI  = 1024;
    const uint32_t A_LO  = A_HI + 128 * ASTR * 2;
    const uint32_t B_HI  = A_LO + 128 * ASTR * 2;
    const uint32_t B_LO  = B_HI + TN * ASTR * 2;

    uint32_t sb = smem_u32(smem);
    int tid = threadIdx.x, wid = tid >> 5, lane = tid & 31;
    int m0 = blockIdx.x * 128;

    if (PRE_BN && tid < 256) {
        float v = (tid < 128) ? g_stats1[2 * HID + tid] : g_stats1[3 * HID + (tid - 128)];
        *(float*)(smem + SM_ST + tid * 4) = v;
    }

    const float* Asrc = PRE_BN ? g_a1 : Aext;
    __half* Cout = PRE_BN ? g_h2h : g_h1h;

    const float* s = (const float*)(smem + SM_ST);
    const float* t = s + 128;
    if (PRE_BN) __syncthreads();
    #pragma unroll
    for (int it = 0; it < 16; ++it) {
        int idx = tid + it * 256;
        int row = idx >> 5;
        int col = (idx & 31) << 2;
        float4 v = make_float4(0.f, 0.f, 0.f, 0.f);
        if (m0 + row < M) v = *(const float4*)&Asrc[(size_t)(m0 + row) * 128 + col];
        if (PRE_BN) {
            v.x = fmaxf(fmaf(v.x, s[col + 0], t[col + 0]), 0.f);
            v.y = fmaxf(fmaf(v.y, s[col + 1], t[col + 1]), 0.f);
            v.z = fmaxf(fmaf(v.z, s[col + 2], t[col + 2]), 0.f);
            v.w = fmaxf(fmaf(v.w, s[col + 3], t[col + 3]), 0.f);
        }
        __nv_bfloat162 h01 = __floats2bfloat162_rn(v.x, v.y);
        __nv_bfloat162 h23 = __floats2bfloat162_rn(v.z, v.w);
        __nv_bfloat162 l01 = __floats2bfloat162_rn(v.x - __bfloat162float(h01.x),
                                                   v.y - __bfloat162float(h01.y));
        __nv_bfloat162 l23 = __floats2bfloat162_rn(v.z - __bfloat162float(h23.x),
                                                   v.w - __bfloat162float(h23.y));
        uint32_t off = (uint32_t)row * (ASTR * 2) + (uint32_t)col * 2;
        *(__nv_bfloat162*)(smem + A_HI + off)     = h01;
        *(__nv_bfloat162*)(smem + A_HI + off + 4) = h23;
        *(__nv_bfloat162*)(smem + A_LO + off)     = l01;
        *(__nv_bfloat162*)(smem + A_LO + off + 4) = l23;
    }
    for (int idx = tid; idx < 128 * TN; idx += 256) {
        int k = idx / TN, n = idx % TN;
        float w = W[idx];
        __nv_bfloat16 hi = __float2bfloat16_rn(w);
        __nv_bfloat16 lo = __float2bfloat16_rn(w - __bfloat162float(hi));
        uint32_t off = (uint32_t)n * (ASTR * 2) + (uint32_t)k * 2;
        *(__nv_bfloat16*)(smem + B_HI + off) = hi;
        *(__nv_bfloat16*)(smem + B_LO + off) = lo;
    }
    __syncthreads();

    constexpr int WN   = TN / 2;
    constexpr int NSUB = WN / 8;
    int m_base = (wid & 3) * 32;
    int n_base = (wid >> 2) * WN;
    int g = lane >> 2, tt = lane & 3;

    float acc[2][NSUB][4];
    #pragma unroll
    for (int mi = 0; mi < 2; mi++)
        #pragma unroll
        for (int ni = 0; ni < NSUB; ni++)
            #pragma unroll
            for (int j = 0; j < 4; j++) acc[mi][ni][j] = 0.f;

    uint32_t a_row = (uint32_t)(m_base + (lane & 15));
    uint32_t a_cb  = (uint32_t)((lane >> 4) * 8);

    #pragma unroll
    for (int term = 0; term < 3; ++term) {
        uint32_t Abase = sb + ((term == 1) ? A_LO : A_HI);
        uint32_t Bbase = ((term == 2) ? B_LO : B_HI);
        #pragma unroll
        for (int ks = 0; ks < 8; ++ks) {
            int k0 = ks * 16;
            uint32_t af[2][4];
            #pragma unroll
            for (int mi = 0; mi < 2; mi++) {
                uint32_t addr = Abase + (a_row + mi * 16) * (ASTR * 2) + (a_cb + k0) * 2;
                ldmatrix_x4(af[mi], addr);
            }
            const char* brow = smem + Bbase + (uint32_t)(n_base + g) * (ASTR * 2) + (uint32_t)(k0 + 2 * tt) * 2;
            #pragma unroll
            for (int ni = 0; ni < NSUB; ni++) {
                uint32_t b0 = *(const uint32_t*)(brow + ni * 8 * (ASTR * 2));
                uint32_t b1 = *(const uint32_t*)(brow + ni * 8 * (ASTR * 2) + 16);
                mma_bf16(acc[0][ni], af[0], b0, b1);
                mma_bf16(acc[1][ni], af[1], b0, b1);
            }
        }
    }

    #pragma unroll
    for (int mi = 0; mi < 2; mi++) {
        int r0 = m0 + m_base + mi * 16 + g;
        int r1 = r0 + 8;
        float d0 = 1.f, d1 = 1.f;
        if (DINV) {
            d0 = (r0 < M) ? g_dinv[r0] : 0.f;
            d1 = (r1 < M) ? g_dinv[r1] : 0.f;
        }
        #pragma unroll
        for (int ni = 0; ni < NSUB; ni++) {
            int col = n_base + ni * 8 + 2 * tt;
            if (r0 < M)
                *(__half2*)&Cout[(size_t)r0 * TN + col] =
                    __floats2half2_rn(acc[mi][ni][0] * d0, acc[mi][ni][1] * d0);
            if (r1 < M)
                *(__half2*)&Cout[(size_t)r1 * TN + col] =
                    __floats2half2_rn(acc[mi][ni][2] * d1, acc[mi][ni][3] * d1);
        }
    }
}

// ---------------- aggregation helpers ----------------
__device__ __forceinline__ float4 h4_to_f4(uint2 u) {
    float2 a = __half22float2(*(__half2*)&u.x);
    float2 b = __half22float2(*(__half2*)&u.y);
    return make_float4(a.x, a.y, b.x, b.y);
}

// ---------------- aggregation, 128 cols (h1 pre-scaled by dinv[src]) ----------------
// Last block also computes BN1 s/t.
__global__ __launch_bounds__(256)
void agg128_kernel(const float* __restrict__ b, const float* __restrict__ gamma,
                   const float* __restrict__ beta, int n, float invN) {
    int gwarp  = (blockIdx.x * blockDim.x + threadIdx.x) >> 5;
    int lane   = threadIdx.x & 31;
    int nwarps = (gridDim.x * blockDim.x) >> 5;
    const uint2* base = (const uint2*)g_h1h;
    float4 bb = ((const float4*)b)[lane];
    float4 sum = make_float4(0, 0, 0, 0), sq = make_float4(0, 0, 0, 0);

    for (int node = gwarp; node < n; node += nwarps) {
        int e0 = g_rowptr[node], e1 = g_rowptr[node + 1];
        float4 acc = h4_to_f4(base[(size_t)node * 32 + lane]);  // self-loop
        int e = e0;
        for (; e + 4 <= e1; e += 4) {
            int i0 = g_col[e], i1 = g_col[e + 1], i2 = g_col[e + 2], i3 = g_col[e + 3];
            float4 v0 = h4_to_f4(base[(size_t)i0 * 32 + lane]);
            float4 v1 = h4_to_f4(base[(size_t)i1 * 32 + lane]);
            float4 v2 = h4_to_f4(base[(size_t)i2 * 32 + lane]);
            float4 v3 = h4_to_f4(base[(size_t)i3 * 32 + lane]);
            acc.x += (v0.x + v1.x) + (v2.x + v3.x);
            acc.y += (v0.y + v1.y) + (v2.y + v3.y);
            acc.z += (v0.z + v1.z) + (v2.z + v3.z);
            acc.w += (v0.w + v1.w) + (v2.w + v3.w);
        }
        for (; e < e1; e++) {
            float4 v = h4_to_f4(base[(size_t)g_col[e] * 32 + lane]);
            acc.x += v.x; acc.y += v.y; acc.z += v.z; acc.w += v.w;
        }
        float d = g_dinv[node];
        float4 o;
        o.x = fmaf(acc.x, d, bb.x); o.y = fmaf(acc.y, d, bb.y);
        o.z = fmaf(acc.z, d, bb.z); o.w = fmaf(acc.w, d, bb.w);
        ((float4*)g_a1)[(size_t)node * 32 + lane] = o;
        sum.x += o.x; sum.y += o.y; sum.z += o.z; sum.w += o.w;
        sq.x += o.x * o.x; sq.y += o.y * o.y; sq.z += o.z * o.z; sq.w += o.w * o.w;
    }
    __shared__ float ssum[HID], ssq[HID];
    int t = threadIdx.x;
    if (t < HID) { ssum[t] = 0.f; ssq[t] = 0.f; }
    __syncthreads();
    int c0 = lane * 4;
    atomicAdd(&ssum[c0 + 0], sum.x); atomicAdd(&ssum[c0 + 1], sum.y);
    atomicAdd(&ssum[c0 + 2], sum.z); atomicAdd(&ssum[c0 + 3], sum.w);
    atomicAdd(&ssq[c0 + 0], sq.x);  atomicAdd(&ssq[c0 + 1], sq.y);
    atomicAdd(&ssq[c0 + 2], sq.z);  atomicAdd(&ssq[c0 + 3], sq.w);
    __syncthreads();
    if (t < HID) {
        atomicAdd(&g_stats1[t], ssum[t]);
        atomicAdd(&g_stats1[HID + t], ssq[t]);
    }
    __threadfence();
    __shared__ int isLast;
    __syncthreads();
    if (t == 0) isLast = (atomicAdd(&g_ctr1, 1) == (int)gridDim.x - 1);
    __syncthreads();
    if (isLast && t < HID) {
        float mean = g_stats1[t] * invN;
        float var  = g_stats1[HID + t] * invN - mean * mean;
        float sc = gamma[t] * rsqrtf(var + EPS);
        g_stats1[2 * HID + t] = sc;
        g_stats1[3 * HID + t] = beta[t] - mean * sc;
    }
}

// ---------------- aggregation, 64 cols + fused grid-barrier BN2 apply ----------------
__global__ __launch_bounds__(256, 4)
void agg64_kernel(const float* __restrict__ b, const float* __restrict__ gamma,
                  const float* __restrict__ beta, float* __restrict__ out,
                  int n, float invN) {
    int gwarp  = (blockIdx.x * blockDim.x + threadIdx.x) >> 5;
    int lane   = threadIdx.x & 31;
    int nwarps = (gridDim.x * blockDim.x) >> 5;
    const __half2* base = (const __half2*)g_h2h;
    float2 bb = ((const float2*)b)[lane];
    float2 sum = make_float2(0, 0), sq = make_float2(0, 0);

    for (int node = gwarp; node < n; node += nwarps) {
        int e0 = g_rowptr[node], e1 = g_rowptr[node + 1];
        float2 acc = __half22float2(base[(size_t)node * 32 + lane]);
        int e = e0;
        for (; e + 4 <= e1; e += 4) {
            int i0 = g_col[e], i1 = g_col[e + 1], i2 = g_col[e + 2], i3 = g_col[e + 3];
            float2 v0 = __half22float2(base[(size_t)i0 * 32 + lane]);
            float2 v1 = __half22float2(base[(size_t)i1 * 32 + lane]);
            float2 v2 = __half22float2(base[(size_t)i2 * 32 + lane]);
            float2 v3 = __half22float2(base[(size_t)i3 * 32 + lane]);
            acc.x += (v0.x + v1.x) + (v2.x + v3.x);
            acc.y += (v0.y + v1.y) + (v2.y + v3.y);
        }
        for (; e < e1; e++) {
            float2 v = __half22float2(base[(size_t)g_col[e] * 32 + lane]);
            acc.x += v.x; acc.y += v.y;
        }
        float d = g_dinv[node];
        float2 o;
        o.x = fmaf(acc.x, d, bb.x); o.y = fmaf(acc.y, d, bb.y);
        ((float2*)out)[(size_t)node * 32 + lane] = o;
        sum.x += o.x; sum.y += o.y;
        sq.x += o.x * o.x; sq.y += o.y * o.y;
    }
    __shared__ float ssum[OUTC], ssq[OUTC];
    __shared__ float sS[OUTC], sT[OUTC];
    int t = threadIdx.x;
    if (t < OUTC) { ssum[t] = 0.f; ssq[t] = 0.f; }
    __syncthreads();
    int c0 = lane * 2;
    atomicAdd(&ssum[c0 + 0], sum.x); atomicAdd(&ssum[c0 + 1], sum.y);
    atomicAdd(&ssq[c0 + 0], sq.x);  atomicAdd(&ssq[c0 + 1], sq.y);
    __syncthreads();
    if (t < OUTC) {
        atomicAdd(&g_stats2[t], ssum[t]);
        atomicAdd(&g_stats2[OUTC + t], ssq[t]);
    }
    __threadfence();
    __shared__ int isLast;
    __syncthreads();
    if (t == 0) isLast = (atomicAdd(&g_ctr2, 1) == (int)gridDim.x - 1);
    __syncthreads();
    if (isLast) {
        if (t < OUTC) {
            float mean = g_stats2[t] * invN;
            float var  = g_stats2[OUTC + t] * invN - mean * mean;
            float sc = gamma[t] * rsqrtf(var + EPS);
            g_stats2[2 * OUTC + t] = sc;
            g_stats2[3 * OUTC + t] = beta[t] - mean * sc;
        }
        __threadfence();
        __syncthreads();
        if (t == 0) atomicExch(&g_flag2, 1);
    }
    // grid barrier: all blocks are resident (launch_bounds(256,4), grid<=592)
    if (t == 0) { while (atomicAdd(&g_flag2, 0) == 0) { } }
    __syncthreads();
    if (t < OUTC) { sS[t] = g_stats2[2 * OUTC + t]; sT[t] = g_stats2[3 * OUTC + t]; }
    __syncthreads();
    // apply BN2 affine in place over partitioned range
    int gtid = blockIdx.x * blockDim.x + t;
    int stride = gridDim.x * blockDim.x;
    int total4 = n * (OUTC / 4);
    float4* o4 = (float4*)out;
    for (int i = gtid; i < total4; i += stride) {
        float4 v = o4[i];
        int c = (i & 15) * 4;
        v.x = fmaf(v.x, sS[c + 0], sT[c + 0]);
        v.y = fmaf(v.y, sS[c + 1], sT[c + 1]);
        v.z = fmaf(v.z, sS[c + 2], sT[c + 2]);
        v.w = fmaf(v.w, sS[c + 3], sT[c + 3]);
        o4[i] = v;
    }
}

extern "C" void kernel_launch(void* const* d_in, const int* in_sizes, int n_in,
                              void* d_out, int out_size) {
    const float* x      = (const float*)d_in[0];
    const float* W1     = (const float*)d_in[1];
    const float* b1     = (const float*)d_in[2];
    const float* gamma1 = (const float*)d_in[3];
    const float* beta1  = (const float*)d_in[4];
    const float* W2     = (const float*)d_in[5];
    const float* b2     = (const float*)d_in[6];
    const float* gamma2 = (const float*)d_in[7];
    const float* beta2  = (const float*)d_in[8];
    const int*   ei     = (const int*)d_in[9];
    float*       out    = (float*)d_out;

    int N = in_sizes[0] / INC;     // 100000
    int E = in_sizes[9] / 2;       // 1600000
    const int* src = ei;
    const int* dst = ei + E;
    float invN = 1.0f / (float)N;

    const int SMEM1 = 1024 + 2 * 128 * ASTR * 2 + 2 * 128 * ASTR * 2;  // 140288
    const int SMEM2 = 1024 + 2 * 128 * ASTR * 2 + 2 * 64 * ASTR * 2;   // 105472

    static cudaStream_t s2 = nullptr;
    static cudaEvent_t  ev0 = nullptr, ev1 = nullptr, evScan = nullptr;
    if (!s2) {
        cudaFuncSetAttribute(mmagemm_kernel<128, false, false>,
                             cudaFuncAttributeMaxDynamicSharedMemorySize, SMEM1);
        cudaFuncSetAttribute(mmagemm_kernel<64, true, true>,
                             cudaFuncAttributeMaxDynamicSharedMemorySize, SMEM2);
        cudaStreamCreateWithFlags(&s2, cudaStreamNonBlocking);
        cudaEventCreateWithFlags(&ev0, cudaEventDisableTiming);
        cudaEventCreateWithFlags(&ev1, cudaEventDisableTiming);
        cudaEventCreateWithFlags(&evScan, cudaEventDisableTiming);
    }

    int nb = (N + 1023) / 1024;
    int gblk = (N + 127) / 128;

    // ---- fork: GEMM1 (pure function of x, W1; no dinv) on side stream ----
    cudaEventRecord(ev0, 0);
    cudaStreamWaitEvent(s2, ev0, 0);
    mmagemm_kernel<128, false, false><<<gblk, 256, SMEM1, s2>>>(x, W1, N);

    // ---- main branch: degrees + scan (produces dinv) ----
    zero_kernel<<<(N + 255) / 256, 256>>>(N);
    count_kernel<<<(E + 255) / 256, 256>>>(dst, E);
    scan1_kernel<<<nb, 1024>>>(N);
    scan3_kernel<<<nb, 1024>>>(N, nb);
    cudaEventRecord(evScan, 0);

    // ---- side: scale h1 by dinv (needs gemm1 + scan3), overlaps with fill ----
    cudaStreamWaitEvent(s2, evScan, 0);
    scaleh1_kernel<<<(N * 16 + 255) / 256, 256, 0, s2>>>(N * 16);
    cudaEventRecord(ev1, s2);

    // ---- main: CSR fill ----
    fill_kernel<<<(E + 255) / 256, 256>>>(src, dst, E);

    // ---- join ----
    cudaStreamWaitEvent(0, ev1, 0);

    // aggregate layer 1 (+bias, +BN1 stats+params)
    agg128_kernel<<<1024, 256>>>(b1, gamma1, beta1, N, invN);
    // h2 = (relu(bn1(a1)) @ W2) * dinv -> fp16
    mmagemm_kernel<64, true, true><<<gblk, 256, SMEM2>>>(nullptr, W2, N);
    // aggregate layer 2 into d_out (+BN2 stats+params+apply, grid-barrier fused)
    agg64_kernel<<<512, 256>>>(b2, gamma2, beta2, out, N, invN);
}

// round 9
// speedup vs baseline: 1.1127x; 1.0243x over previous
#include <cuda_runtime.h>
#include <cuda_bf16.h>
#include <cuda_fp16.h>
#include <cstdint>

#define NMAX 100000
#define EMAX 1600000
#define INC  128
#define HID  128
#define OUTC 64
#define EPS  1e-5f

// ---------------- scratch (no allocations allowed) ----------------
__device__ int    g_cnt[NMAX];
__device__ int    g_rowptr[NMAX + 1];
__device__ int    g_fill[NMAX];
__device__ int    g_col[EMAX];
__device__ float  g_dinv[NMAX];
__device__ int    g_bsum[128];
__device__ int    g_ctr1, g_ctr2, g_flag2;
__device__ __half g_h1h[(size_t)NMAX * HID];   // (x@W1)*dinv[row], fp16
__device__ __half g_a1h[(size_t)NMAX * HID];   // aggregated layer-1 (pre-BN), fp16
__device__ __half g_h2h[(size_t)NMAX * OUTC];  // (relu(bn1)@W2)*dinv[row], fp16
__device__ float  g_stats1[4 * HID];           // sum | sq | s | t
__device__ float  g_stats2[4 * OUTC];

// ---------------- helpers ----------------
__device__ __forceinline__ uint32_t smem_u32(const void* p) {
    uint32_t a;
    asm("{ .reg .u64 t; cvta.to.shared.u64 t, %1; cvt.u32.u64 %0, t; }" : "=r"(a) : "l"(p));
    return a;
}
__device__ __forceinline__ void ldmatrix_x4(uint32_t* r, uint32_t addr) {
    asm volatile("ldmatrix.sync.aligned.m8n8.x4.shared.b16 {%0,%1,%2,%3}, [%4];"
                 : "=r"(r[0]), "=r"(r[1]), "=r"(r[2]), "=r"(r[3]) : "r"(addr));
}
__device__ __forceinline__ void mma_bf16(float* c, const uint32_t* a, uint32_t b0, uint32_t b1) {
    asm volatile(
        "mma.sync.aligned.m16n8k16.row.col.f32.bf16.bf16.f32 "
        "{%0,%1,%2,%3}, {%4,%5,%6,%7}, {%8,%9}, {%0,%1,%2,%3};"
        : "+f"(c[0]), "+f"(c[1]), "+f"(c[2]), "+f"(c[3])
        : "r"(a[0]), "r"(a[1]), "r"(a[2]), "r"(a[3]), "r"(b0), "r"(b1));
}

// ---------------- init ----------------
__global__ void zero_kernel(int n) {
    int i = blockIdx.x * blockDim.x + threadIdx.x;
    if (i < n)        g_cnt[i] = 0;
    if (i < 4 * HID)  g_stats1[i] = 0.f;
    if (i < 4 * OUTC) g_stats2[i] = 0.f;
    if (i == 0) { g_ctr1 = 0; g_ctr2 = 0; g_flag2 = 0; }
}

// ---------------- degree count ----------------
__global__ void count_kernel(const int* __restrict__ dst, int E) {
    int i = blockIdx.x * blockDim.x + threadIdx.x;
    if (i < E) atomicAdd(&g_cnt[dst[i]], 1);
}

// ---------------- 2-pass parallel scan ----------------
__global__ void scan1_kernel(int n) {
    __shared__ int ws[32];
    int tid = threadIdx.x, lane = tid & 31, w = tid >> 5;
    int i = blockIdx.x * 1024 + tid;
    int v = (i < n) ? g_cnt[i] : 0;
    int x = v;
    #pragma unroll
    for (int off = 1; off < 32; off <<= 1) {
        int y = __shfl_up_sync(0xffffffffu, x, off);
        if (lane >= off) x += y;
    }
    if (lane == 31) ws[w] = x;
    __syncthreads();
    if (w == 0) {
        int y = ws[lane];
        #pragma unroll
        for (int off = 1; off < 32; off <<= 1) {
            int z = __shfl_up_sync(0xffffffffu, y, off);
            if (lane >= off) y += z;
        }
        ws[lane] = y;
    }
    __syncthreads();
    int incl = x + (w ? ws[w - 1] : 0);
    if (i < n) g_fill[i] = incl - v;
    if (tid == 1023) g_bsum[blockIdx.x] = incl;
}
__global__ void scan3_kernel(int n, int nb) {
    __shared__ int excl[128];
    __shared__ int wsum[4];
    int tid = threadIdx.x, lane = tid & 31, w = tid >> 5;
    int xv = 0, vv = 0;
    if (tid < 128) {
        vv = (tid < nb) ? g_bsum[tid] : 0;
        xv = vv;
        #pragma unroll
        for (int off = 1; off < 32; off <<= 1) {
            int y = __shfl_up_sync(0xffffffffu, xv, off);
            if (lane >= off) xv += y;
        }
        if (lane == 31) wsum[w] = xv;
    }
    __syncthreads();
    if (tid < 128) {
        int add = 0;
        #pragma unroll
        for (int j = 0; j < 4; j++) if (j < w) add += wsum[j];
        excl[tid] = xv - vv + add;
    }
    __syncthreads();
    int off = excl[blockIdx.x];
    int i = blockIdx.x * 1024 + tid;
    if (i < n) {
        int c = g_cnt[i];
        int ex = g_fill[i] + off;
        g_fill[i] = ex;
        g_rowptr[i + 1] = ex + c;
        g_dinv[i] = rsqrtf((float)(c + 1));
        if (i == 0) g_rowptr[0] = 0;
    }
}

// ---------------- CSR fill ----------------
__global__ void fill_kernel(const int* __restrict__ src, const int* __restrict__ dst, int E) {
    int i = blockIdx.x * blockDim.x + threadIdx.x;
    if (i < E) {
        int d = dst[i];
        int pos = atomicAdd(&g_fill[d], 1);
        g_col[pos] = src[i];
    }
}

// ---------------- HMMA bf16 GEMM ----------------
// A,W split into bf16 hi/lo; D = Ah*Wh + Al*Wh + Ah*Wl (fp32 accum).
// PRE_BN: A is fp16 g_a1h with relu(a*s[k]+t[k]) folded into the load.
// Epilogue scale: DINVC -> rsqrt(cnt+1) from g_cnt; DINV -> g_dinv.
#define ASTR 136
template <int TN, bool PRE_BN, bool DINVC, bool DINV>
__global__ __launch_bounds__(256)
void mmagemm_kernel(const float* __restrict__ Aext, const float* __restrict__ W, int M) {
    extern __shared__ char smem[];
    const uint32_t SM_ST = 0;
    const uint32_t A_HI  = 1024;
    const uint32_t A_LO  = A_HI + 128 * ASTR * 2;
    const uint32_t B_HI  = A_LO + 128 * ASTR * 2;
    const uint32_t B_LO  = B_HI + TN * ASTR * 2;

    uint32_t sb = smem_u32(smem);
    int tid = threadIdx.x, wid = tid >> 5, lane = tid & 31;
    int m0 = blockIdx.x * 128;

    if (PRE_BN && tid < 256) {
        float v = (tid < 128) ? g_stats1[2 * HID + tid] : g_stats1[3 * HID + (tid - 128)];
        *(float*)(smem + SM_ST + tid * 4) = v;
    }

    __half* Cout = PRE_BN ? g_h2h : g_h1h;
    const float* s = (const float*)(smem + SM_ST);
    const float* t = s + 128;
    if (PRE_BN) __syncthreads();

    if (PRE_BN) {
        // A tile from fp16 g_a1h: 128x128 halves, 8 uint4 iterations/thread
        #pragma unroll
        for (int it = 0; it < 8; ++it) {
            int idx = tid + it * 256;         // 0..2047
            int row = idx >> 4;               // 16 uint4 per row
            int c8  = (idx & 15) * 8;
            uint4 u = make_uint4(0, 0, 0, 0);
            if (m0 + row < M) u = *(const uint4*)&g_a1h[(size_t)(m0 + row) * 128 + c8];
            const __half2* hp = (const __half2*)&u;
            uint32_t off = (uint32_t)row * (ASTR * 2) + (uint32_t)c8 * 2;
            #pragma unroll
            for (int j = 0; j < 4; j++) {
                float2 f = __half22float2(hp[j]);
                int k = c8 + 2 * j;
                f.x = fmaxf(fmaf(f.x, s[k + 0], t[k + 0]), 0.f);
                f.y = fmaxf(fmaf(f.y, s[k + 1], t[k + 1]), 0.f);
                __nv_bfloat162 h = __floats2bfloat162_rn(f.x, f.y);
                __nv_bfloat162 l = __floats2bfloat162_rn(f.x - __bfloat162float(h.x),
                                                         f.y - __bfloat162float(h.y));
                *(__nv_bfloat162*)(smem + A_HI + off + 4 * j) = h;
                *(__nv_bfloat162*)(smem + A_LO + off + 4 * j) = l;
            }
        }
    } else {
        // A tile from fp32 Aext
        #pragma unroll
        for (int it = 0; it < 16; ++it) {
            int idx = tid + it * 256;
            int row = idx >> 5;
            int col = (idx & 31) << 2;
            float4 v = make_float4(0.f, 0.f, 0.f, 0.f);
            if (m0 + row < M) v = *(const float4*)&Aext[(size_t)(m0 + row) * 128 + col];
            __nv_bfloat162 h01 = __floats2bfloat162_rn(v.x, v.y);
            __nv_bfloat162 h23 = __floats2bfloat162_rn(v.z, v.w);
            __nv_bfloat162 l01 = __floats2bfloat162_rn(v.x - __bfloat162float(h01.x),
                                                       v.y - __bfloat162float(h01.y));
            __nv_bfloat162 l23 = __floats2bfloat162_rn(v.z - __bfloat162float(h23.x),
                                                       v.w - __bfloat162float(h23.y));
            uint32_t off = (uint32_t)row * (ASTR * 2) + (uint32_t)col * 2;
            *(__nv_bfloat162*)(smem + A_HI + off)     = h01;
            *(__nv_bfloat162*)(smem + A_HI + off + 4) = h23;
            *(__nv_bfloat162*)(smem + A_LO + off)     = l01;
            *(__nv_bfloat162*)(smem + A_LO + off + 4) = l23;
        }
    }
    for (int idx = tid; idx < 128 * TN; idx += 256) {
        int k = idx / TN, n = idx % TN;
        float w = W[idx];
        __nv_bfloat16 hi = __float2bfloat16_rn(w);
        __nv_bfloat16 lo = __float2bfloat16_rn(w - __bfloat162float(hi));
        uint32_t off = (uint32_t)n * (ASTR * 2) + (uint32_t)k * 2;
        *(__nv_bfloat16*)(smem + B_HI + off) = hi;
        *(__nv_bfloat16*)(smem + B_LO + off) = lo;
    }
    __syncthreads();

    constexpr int WN   = TN / 2;
    constexpr int NSUB = WN / 8;
    int m_base = (wid & 3) * 32;
    int n_base = (wid >> 2) * WN;
    int g = lane >> 2, tt = lane & 3;

    float acc[2][NSUB][4];
    #pragma unroll
    for (int mi = 0; mi < 2; mi++)
        #pragma unroll
        for (int ni = 0; ni < NSUB; ni++)
            #pragma unroll
            for (int j = 0; j < 4; j++) acc[mi][ni][j] = 0.f;

    uint32_t a_row = (uint32_t)(m_base + (lane & 15));
    uint32_t a_cb  = (uint32_t)((lane >> 4) * 8);

    #pragma unroll
    for (int term = 0; term < 3; ++term) {
        uint32_t Abase = sb + ((term == 1) ? A_LO : A_HI);
        uint32_t Bbase = ((term == 2) ? B_LO : B_HI);
        #pragma unroll
        for (int ks = 0; ks < 8; ++ks) {
            int k0 = ks * 16;
            uint32_t af[2][4];
            #pragma unroll
            for (int mi = 0; mi < 2; mi++) {
                uint32_t addr = Abase + (a_row + mi * 16) * (ASTR * 2) + (a_cb + k0) * 2;
                ldmatrix_x4(af[mi], addr);
            }
            const char* brow = smem + Bbase + (uint32_t)(n_base + g) * (ASTR * 2) + (uint32_t)(k0 + 2 * tt) * 2;
            #pragma unroll
            for (int ni = 0; ni < NSUB; ni++) {
                uint32_t b0 = *(const uint32_t*)(brow + ni * 8 * (ASTR * 2));
                uint32_t b1 = *(const uint32_t*)(brow + ni * 8 * (ASTR * 2) + 16);
                mma_bf16(acc[0][ni], af[0], b0, b1);
                mma_bf16(acc[1][ni], af[1], b0, b1);
            }
        }
    }

    #pragma unroll
    for (int mi = 0; mi < 2; mi++) {
        int r0 = m0 + m_base + mi * 16 + g;
        int r1 = r0 + 8;
        float d0 = 1.f, d1 = 1.f;
        if (DINVC) {
            d0 = (r0 < M) ? rsqrtf((float)(g_cnt[r0] + 1)) : 0.f;
            d1 = (r1 < M) ? rsqrtf((float)(g_cnt[r1] + 1)) : 0.f;
        }
        if (DINV) {
            d0 = (r0 < M) ? g_dinv[r0] : 0.f;
            d1 = (r1 < M) ? g_dinv[r1] : 0.f;
        }
        #pragma unroll
        for (int ni = 0; ni < NSUB; ni++) {
            int col = n_base + ni * 8 + 2 * tt;
            if (r0 < M)
                *(__half2*)&Cout[(size_t)r0 * TN + col] =
                    __floats2half2_rn(acc[mi][ni][0] * d0, acc[mi][ni][1] * d0);
            if (r1 < M)
                *(__half2*)&Cout[(size_t)r1 * TN + col] =
                    __floats2half2_rn(acc[mi][ni][2] * d1, acc[mi][ni][3] * d1);
        }
    }
}

// ---------------- aggregation helpers ----------------
__device__ __forceinline__ float4 h4_to_f4(uint2 u) {
    float2 a = __half22float2(*(__half2*)&u.x);
    float2 b = __half22float2(*(__half2*)&u.y);
    return make_float4(a.x, a.y, b.x, b.y);
}

// ---------------- aggregation, 128 cols (h1 pre-scaled); out fp16; fused BN1 params ----------------
__global__ __launch_bounds__(256)
void agg128_kernel(const float* __restrict__ b, const float* __restrict__ gamma,
                   const float* __restrict__ beta, int n, float invN) {
    int gwarp  = (blockIdx.x * blockDim.x + threadIdx.x) >> 5;
    int lane   = threadIdx.x & 31;
    int nwarps = (gridDim.x * blockDim.x) >> 5;
    const uint2* base = (const uint2*)g_h1h;
    float4 bb = ((const float4*)b)[lane];
    float4 sum = make_float4(0, 0, 0, 0), sq = make_float4(0, 0, 0, 0);

    for (int node = gwarp; node < n; node += nwarps) {
        int e0 = g_rowptr[node], e1 = g_rowptr[node + 1];
        float4 acc = h4_to_f4(base[(size_t)node * 32 + lane]);  // self-loop
        int e = e0;
        for (; e + 4 <= e1; e += 4) {
            int i0 = g_col[e], i1 = g_col[e + 1], i2 = g_col[e + 2], i3 = g_col[e + 3];
            float4 v0 = h4_to_f4(base[(size_t)i0 * 32 + lane]);
            float4 v1 = h4_to_f4(base[(size_t)i1 * 32 + lane]);
            float4 v2 = h4_to_f4(base[(size_t)i2 * 32 + lane]);
            float4 v3 = h4_to_f4(base[(size_t)i3 * 32 + lane]);
            acc.x += (v0.x + v1.x) + (v2.x + v3.x);
            acc.y += (v0.y + v1.y) + (v2.y + v3.y);
            acc.z += (v0.z + v1.z) + (v2.z + v3.z);
            acc.w += (v0.w + v1.w) + (v2.w + v3.w);
        }
        for (; e < e1; e++) {
            float4 v = h4_to_f4(base[(size_t)g_col[e] * 32 + lane]);
            acc.x += v.x; acc.y += v.y; acc.z += v.z; acc.w += v.w;
        }
        float d = g_dinv[node];
        float4 o;
        o.x = fmaf(acc.x, d, bb.x); o.y = fmaf(acc.y, d, bb.y);
        o.z = fmaf(acc.z, d, bb.z); o.w = fmaf(acc.w, d, bb.w);
        uint2 st;
        *(__half2*)&st.x = __floats2half2_rn(o.x, o.y);
        *(__half2*)&st.y = __floats2half2_rn(o.z, o.w);
        ((uint2*)g_a1h)[(size_t)node * 32 + lane] = st;
        sum.x += o.x; sum.y += o.y; sum.z += o.z; sum.w += o.w;
        sq.x += o.x * o.x; sq.y += o.y * o.y; sq.z += o.z * o.z; sq.w += o.w * o.w;
    }
    __shared__ float ssum[HID], ssq[HID];
    int t = threadIdx.x;
    if (t < HID) { ssum[t] = 0.f; ssq[t] = 0.f; }
    __syncthreads();
    int c0 = lane * 4;
    atomicAdd(&ssum[c0 + 0], sum.x); atomicAdd(&ssum[c0 + 1], sum.y);
    atomicAdd(&ssum[c0 + 2], sum.z); atomicAdd(&ssum[c0 + 3], sum.w);
    atomicAdd(&ssq[c0 + 0], sq.x);  atomicAdd(&ssq[c0 + 1], sq.y);
    atomicAdd(&ssq[c0 + 2], sq.z);  atomicAdd(&ssq[c0 + 3], sq.w);
    __syncthreads();
    if (t < HID) {
        atomicAdd(&g_stats1[t], ssum[t]);
        atomicAdd(&g_stats1[HID + t], ssq[t]);
    }
    __threadfence();
    __shared__ int isLast;
    __syncthreads();
    if (t == 0) isLast = (atomicAdd(&g_ctr1, 1) == (int)gridDim.x - 1);
    __syncthreads();
    if (isLast && t < HID) {
        float mean = g_stats1[t] * invN;
        float var  = g_stats1[HID + t] * invN - mean * mean;
        float sc = gamma[t] * rsqrtf(var + EPS);
        g_stats1[2 * HID + t] = sc;
        g_stats1[3 * HID + t] = beta[t] - mean * sc;
    }
}

// ---------------- aggregation, 64 cols + fused grid-barrier BN2 apply ----------------
__global__ __launch_bounds__(256, 4)
void agg64_kernel(const float* __restrict__ b, const float* __restrict__ gamma,
                  const float* __restrict__ beta, float* __restrict__ out,
                  int n, float invN) {
    int gwarp  = (blockIdx.x * blockDim.x + threadIdx.x) >> 5;
    int lane   = threadIdx.x & 31;
    int nwarps = (gridDim.x * blockDim.x) >> 5;
    const __half2* base = (const __half2*)g_h2h;
    float2 bb = ((const float2*)b)[lane];
    float2 sum = make_float2(0, 0), sq = make_float2(0, 0);

    for (int node = gwarp; node < n; node += nwarps) {
        int e0 = g_rowptr[node], e1 = g_rowptr[node + 1];
        float2 acc = __half22float2(base[(size_t)node * 32 + lane]);
        int e = e0;
        for (; e + 4 <= e1; e += 4) {
            int i0 = g_col[e], i1 = g_col[e + 1], i2 = g_col[e + 2], i3 = g_col[e + 3];
            float2 v0 = __half22float2(base[(size_t)i0 * 32 + lane]);
            float2 v1 = __half22float2(base[(size_t)i1 * 32 + lane]);
            float2 v2 = __half22float2(base[(size_t)i2 * 32 + lane]);
            float2 v3 = __half22float2(base[(size_t)i3 * 32 + lane]);
            acc.x += (v0.x + v1.x) + (v2.x + v3.x);
            acc.y += (v0.y + v1.y) + (v2.y + v3.y);
        }
        for (; e < e1; e++) {
            float2 v = __half22float2(base[(size_t)g_col[e] * 32 + lane]);
            acc.x += v.x; acc.y += v.y;
        }
        float d = g_dinv[node];
        float2 o;
        o.x = fmaf(acc.x, d, bb.x); o.y = fmaf(acc.y, d, bb.y);
        ((float2*)out)[(size_t)node * 32 + lane] = o;
        sum.x += o.x; sum.y += o.y;
        sq.x += o.x * o.x; sq.y += o.y * o.y;
    }
    __shared__ float ssum[OUTC], ssq[OUTC];
    __shared__ float sS[OUTC], sT[OUTC];
    int t = threadIdx.x;
    if (t < OUTC) { ssum[t] = 0.f; ssq[t] = 0.f; }
    __syncthreads();
    int c0 = lane * 2;
    atomicAdd(&ssum[c0 + 0], sum.x); atomicAdd(&ssum[c0 + 1], sum.y);
    atomicAdd(&ssq[c0 + 0], sq.x);  atomicAdd(&ssq[c0 + 1], sq.y);
    __syncthreads();
    if (t < OUTC) {
        atomicAdd(&g_stats2[t], ssum[t]);
        atomicAdd(&g_stats2[OUTC + t], ssq[t]);
    }
    __threadfence();
    __shared__ int isLast;
    __syncthreads();
    if (t == 0) isLast = (atomicAdd(&g_ctr2, 1) == (int)gridDim.x - 1);
    __syncthreads();
    if (isLast) {
        if (t < OUTC) {
            float mean = g_stats2[t] * invN;
            float var  = g_stats2[OUTC + t] * invN - mean * mean;
            float sc = gamma[t] * rsqrtf(var + EPS);
            g_stats2[2 * OUTC + t] = sc;
            g_stats2[3 * OUTC + t] = beta[t] - mean * sc;
        }
        __threadfence();
        __syncthreads();
        if (t == 0) atomicExch(&g_flag2, 1);
    }
    if (t == 0) { while (atomicAdd(&g_flag2, 0) == 0) { } }
    __syncthreads();
    if (t < OUTC) { sS[t] = g_stats2[2 * OUTC + t]; sT[t] = g_stats2[3 * OUTC + t]; }
    __syncthreads();
    int gtid = blockIdx.x * blockDim.x + t;
    int stride = gridDim.x * blockDim.x;
    int total4 = n * (OUTC / 4);
    float4* o4 = (float4*)out;
    for (int i = gtid; i < total4; i += stride) {
        float4 v = o4[i];
        int c = (i & 15) * 4;
        v.x = fmaf(v.x, sS[c + 0], sT[c + 0]);
        v.y = fmaf(v.y, sS[c + 1], sT[c + 1]);
        v.z = fmaf(v.z, sS[c + 2], sT[c + 2]);
        v.w = fmaf(v.w, sS[c + 3], sT[c + 3]);
        o4[i] = v;
    }
}

extern "C" void kernel_launch(void* const* d_in, const int* in_sizes, int n_in,
                              void* d_out, int out_size) {
    const float* x      = (const float*)d_in[0];
    const float* W1     = (const float*)d_in[1];
    const float* b1     = (const float*)d_in[2];
    const float* gamma1 = (const float*)d_in[3];
    const float* beta1  = (const float*)d_in[4];
    const float* W2     = (const float*)d_in[5];
    const float* b2     = (const float*)d_in[6];
    const float* gamma2 = (const float*)d_in[7];
    const float* beta2  = (const float*)d_in[8];
    const int*   ei     = (const int*)d_in[9];
    float*       out    = (float*)d_out;

    int N = in_sizes[0] / INC;     // 100000
    int E = in_sizes[9] / 2;       // 1600000
    const int* src = ei;
    const int* dst = ei + E;
    float invN = 1.0f / (float)N;

    const int SMEM1 = 1024 + 2 * 128 * ASTR * 2 + 2 * 128 * ASTR * 2;  // 140288
    const int SMEM2 = 1024 + 2 * 128 * ASTR * 2 + 2 * 64 * ASTR * 2;   // 105472

    static cudaStream_t s2 = nullptr;
    static cudaEvent_t  evC = nullptr, ev1 = nullptr;
    if (!s2) {
        cudaFuncSetAttribute(mmagemm_kernel<128, false, true, false>,
                             cudaFuncAttributeMaxDynamicSharedMemorySize, SMEM1);
        cudaFuncSetAttribute(mmagemm_kernel<64, true, false, true>,
                             cudaFuncAttributeMaxDynamicSharedMemorySize, SMEM2);
        cudaStreamCreateWithFlags(&s2, cudaStreamNonBlocking);
        cudaEventCreateWithFlags(&evC, cudaEventDisableTiming);
        cudaEventCreateWithFlags(&ev1, cudaEventDisableTiming);
    }

    int nb = (N + 1023) / 1024;
    int gblk = (N + 127) / 128;

    // ---- main: degree counts ----
    zero_kernel<<<(N + 255) / 256, 256>>>(N);
    count_kernel<<<(E + 255) / 256, 256>>>(dst, E);
    cudaEventRecord(evC, 0);

    // ---- side: GEMM1 with dinv folded from counts ----
    cudaStreamWaitEvent(s2, evC, 0);
    mmagemm_kernel<128, false, true, false><<<gblk, 256, SMEM1, s2>>>(x, W1, N);
    cudaEventRecord(ev1, s2);

    // ---- main: scan + fill (overlaps GEMM1) ----
    scan1_kernel<<<nb, 1024>>>(N);
    scan3_kernel<<<nb, 1024>>>(N, nb);
    fill_kernel<<<(E + 255) / 256, 256>>>(src, dst, E);

    // ---- join ----
    cudaStreamWaitEvent(0, ev1, 0);

    // aggregate layer 1 (+bias, +BN1 stats+params) -> fp16 a1
    agg128_kernel<<<1024, 256>>>(b1, gamma1, beta1, N, invN);
    // h2 = (relu(bn1(a1)) @ W2) * dinv -> fp16
    mmagemm_kernel<64, true, false, true><<<gblk, 256, SMEM2>>>(nullptr, W2, N);
    // aggregate layer 2 into d_out (+BN2 stats+params+apply)
    agg64_kernel<<<512, 256>>>(b2, gamma2, beta2, out, N, invN);
}